// round 6
// baseline (speedup 1.0000x reference)
#include <cuda_runtime.h>

#define B_    64
#define S_    512
#define DIN   512
#define NCAP  32
#define DCAP  64
#define EPSQ  1e-7f

// ---------------- scratch (device globals; no allocations) ----------------
__device__ float g_Wt[NCAP * DCAP * DIN];      // W transposed: [n][d][i]
__device__ float g_tp[4 * B_ * DIN];           // partial column sums of U
__device__ float g_w[B_ * DIN * NCAP];         // w[b][i][n]
__device__ float g_l[2 * B_ * S_ * NCAP];      // raw logit partials [ihalf][b][s][n]
__device__ float g_vp[2 * B_ * NCAP * DIN];    // v partials [shalf][b][n][i]

// ---------------- prep: blocks 0..255 transpose W, 256..511 colsum U ----------------
__global__ __launch_bounds__(256) void prep_k(const float* __restrict__ U,
                                              const float* __restrict__ W) {
    int t = threadIdx.x;
    if (blockIdx.x < 256) {
        int n  = blockIdx.x >> 3;
        int i0 = (blockIdx.x & 7) * 64;
        __shared__ float sm[64 * 65];
        #pragma unroll
        for (int r = 0; r < 16; ++r) {
            int idx = r * 256 + t;
            int d = idx & 63, ii = idx >> 6;
            sm[d * 65 + ii] = W[(size_t)(i0 + ii) * 2048 + n * 64 + d];
        }
        __syncthreads();
        #pragma unroll
        for (int r = 0; r < 16; ++r) {
            int idx = r * 256 + t;
            int ii = idx & 63, d = idx >> 6;
            g_Wt[((size_t)n * 64 + d) * 512 + i0 + ii] = sm[d * 65 + ii];
        }
    } else {
        int idx = blockIdx.x - 256;
        int b = idx & 63, sc = idx >> 6;
        const float2* p = (const float2*)(U + ((size_t)b * S_ + sc * 128) * DIN) + t;
        float2 a = make_float2(0.f, 0.f);
        #pragma unroll 8
        for (int s = 0; s < 128; ++s) {
            float2 f = p[(size_t)s * 256];
            a.x += f.x; a.y += f.y;
        }
        *(float2*)(g_tp + ((size_t)sc * B_ + b) * DIN + t * 2) = a;
    }
}

// ---------------- fused out + w ----------------
__global__ __launch_bounds__(512) void outw_k(float* __restrict__ out, int bcast, int dow) {
    int n  = blockIdx.x;
    int b0 = blockIdx.y * 8;
    __shared__ __align__(16) float sv[8][DIN];
    __shared__ float so[8][DCAP];
    int t = threadIdx.x, w = t >> 5, lane = t & 31;
    const float* Wn = g_Wt + (size_t)n * DCAP * DIN;

    #pragma unroll
    for (int r = 0; r < 8; ++r) {
        int idx = r * 512 + t;
        int bb = idx >> 9, pos = idx & 511;
        int b = b0 + bb;
        float val;
        if (bcast)
            val = g_tp[(size_t)b * DIN + pos]
                + g_tp[((size_t)B_ + b) * DIN + pos]
                + g_tp[((size_t)2 * B_ + b) * DIN + pos]
                + g_tp[((size_t)3 * B_ + b) * DIN + pos];
        else
            val = g_vp[((size_t)b * NCAP + n) * DIN + pos]
                + g_vp[((size_t)(B_ + b) * NCAP + n) * DIN + pos];
        sv[bb][pos] = val;
    }
    __syncthreads();

    #pragma unroll
    for (int r = 0; r < 4; ++r) {
        int d = r * 16 + w;
        const float4* wp = (const float4*)(Wn + (size_t)d * DIN);
        float acc[8] = {};
        #pragma unroll
        for (int q = 0; q < 4; ++q) {
            float4 wv = wp[lane + q * 32];
            #pragma unroll
            for (int bb = 0; bb < 8; ++bb) {
                float4 vv = ((const float4*)sv[bb])[lane + q * 32];
                acc[bb] += wv.x * vv.x + wv.y * vv.y + wv.z * vv.z + wv.w * vv.w;
            }
        }
        #pragma unroll
        for (int bb = 0; bb < 8; ++bb) {
            #pragma unroll
            for (int off = 16; off; off >>= 1)
                acc[bb] += __shfl_xor_sync(0xffffffffu, acc[bb], off);
        }
        if (lane == 0) {
            #pragma unroll
            for (int bb = 0; bb < 8; ++bb) so[bb][d] = acc[bb];
        }
    }
    __syncthreads();

    if (w < 8) {
        int b = b0 + w;
        float o1 = so[w][lane], o2 = so[w][lane + 32];
        if (bcast) { o1 *= (1.f / 32.f); o2 *= (1.f / 32.f); }
        float sq = o1 * o1 + o2 * o2;
        #pragma unroll
        for (int off = 16; off; off >>= 1) sq += __shfl_xor_sync(0xffffffffu, sq, off);
        float rn = rsqrtf(sq + EPSQ);
        o1 *= rn; o2 *= rn;
        out[((size_t)b * NCAP + n) * DCAP + lane]      = o1;
        out[((size_t)b * NCAP + n) * DCAP + lane + 32] = o2;
        so[w][lane]      = o1;
        so[w][lane + 32] = o2;
    }
    __syncthreads();

    if (dow) {
        int i = t;
        float acc[8] = {};
        #pragma unroll 8
        for (int d = 0; d < DCAP; ++d) {
            float wt = Wn[(size_t)d * DIN + i];
            #pragma unroll
            for (int bb = 0; bb < 8; ++bb) acc[bb] += so[bb][d] * wt;
        }
        #pragma unroll
        for (int bb = 0; bb < 8; ++bb)
            g_w[((size_t)(b0 + bb) * DIN + i) * NCAP + n] = acc[bb];
    }
}

// ---------------- logit partials: tile 256s x 32n over 256 i's ----------------
// grid (2 s-tiles, 2 i-halves, 64 b) = 256 blocks, thread 8s x 4n.
__global__ __launch_bounds__(256, 2) void blog_k(const float* __restrict__ U) {
    int s0 = blockIdx.x * 256;
    int ih = blockIdx.y * 256;
    int b  = blockIdx.z;
    __shared__ __align__(16) float su[256 * 36];  // [s][k]
    __shared__ __align__(16) float sw[32 * 36];   // [k][n]
    int t  = threadIdx.x;
    int tn = (t & 7) * 4, ts = (t >> 3) * 8;
    int lrow = t >> 3, lk = (t & 7) * 4;
    const float* Ub    = U   + (size_t)b * S_ * DIN + ih;
    const float* wbase = g_w + (size_t)b * DIN * NCAP + (size_t)ih * NCAP;
    float4 ua[8], wv;
    #pragma unroll
    for (int j = 0; j < 8; ++j)
        ua[j] = *(const float4*)(Ub + (size_t)(s0 + lrow + 32 * j) * DIN + lk);
    wv = *(const float4*)(wbase + (size_t)lrow * NCAP + tn);
    float acc[8][4] = {};
    #pragma unroll 1
    for (int c = 0; c < 8; ++c) {
        __syncthreads();
        #pragma unroll
        for (int j = 0; j < 8; ++j)
            *(float4*)&su[(lrow + 32 * j) * 36 + lk] = ua[j];
        *(float4*)&sw[lrow * 36 + tn] = wv;
        __syncthreads();
        if (c < 7) {
            int k0 = (c + 1) * 32;
            #pragma unroll
            for (int j = 0; j < 8; ++j)
                ua[j] = *(const float4*)(Ub + (size_t)(s0 + lrow + 32 * j) * DIN + k0 + lk);
            wv = *(const float4*)(wbase + (size_t)(k0 + lrow) * NCAP + tn);
        }
        #pragma unroll
        for (int kk = 0; kk < 32; kk += 4) {
            float4 wv4[4], sv4[8];
            #pragma unroll
            for (int q = 0; q < 4; ++q) wv4[q] = *(const float4*)&sw[(kk + q) * 36 + tn];
            #pragma unroll
            for (int x = 0; x < 8; ++x) sv4[x] = *(const float4*)&su[(ts + x) * 36 + kk];
            #pragma unroll
            for (int q = 0; q < 4; ++q) {
                float4 wq = wv4[q];
                #pragma unroll
                for (int x = 0; x < 8; ++x) {
                    float a = (q == 0) ? sv4[x].x : (q == 1) ? sv4[x].y
                            : (q == 2) ? sv4[x].z : sv4[x].w;
                    acc[x][0] += a * wq.x; acc[x][1] += a * wq.y;
                    acc[x][2] += a * wq.z; acc[x][3] += a * wq.w;
                }
            }
        }
    }
    float* lb = g_l + (((size_t)blockIdx.y * B_ + b) * S_ + s0) * NCAP;
    #pragma unroll
    for (int x = 0; x < 8; ++x)
        *(float4*)(lb + (size_t)(ts + x) * NCAP + tn) =
            make_float4(acc[x][0], acc[x][1], acc[x][2], acc[x][3]);
}

// ---------------- v partials: tile 32n x 256i over 256 s's; softmax fused in loader ----
// grid (2 i-tiles, 2 s-halves, 64 b) = 256 blocks, thread 4n x 8i.
__global__ __launch_bounds__(256, 2) void v_k(const float* __restrict__ U) {
    int i0 = blockIdx.x * 256;
    int sh = blockIdx.y * 256;
    int b  = blockIdx.z;
    __shared__ __align__(16) float su[32 * 260];  // [s][i]
    __shared__ __align__(16) float sc[32 * 36];   // [s][n]
    int t  = threadIdx.x;
    int tn = (t & 7) * 4, ti = (t >> 3) * 8;
    int s_u = t >> 3, li = (t & 7) * 4;
    const float* Ub = U + (size_t)b * S_ * DIN;
    const float* l0 = g_l + ((size_t)b * S_ + sh) * NCAP;
    const float* l1 = g_l + (((size_t)B_ + b) * S_ + sh) * NCAP;
    float4 uv[8], ca, cbv;
    #pragma unroll
    for (int j = 0; j < 8; ++j)
        uv[j] = *(const float4*)(Ub + (size_t)(sh + s_u) * DIN + i0 + li + 32 * j);
    ca  = *(const float4*)(l0 + (size_t)s_u * NCAP + tn);
    cbv = *(const float4*)(l1 + (size_t)s_u * NCAP + tn);
    float acc[4][8] = {};
    #pragma unroll 1
    for (int c = 0; c < 8; ++c) {
        __syncthreads();
        #pragma unroll
        for (int j = 0; j < 8; ++j)
            *(float4*)&su[s_u * 260 + li + 32 * j] = uv[j];
        {   // combine logit halves + softmax over n (8 lanes share s-row; xor 1,2,4)
            float v0 = ca.x + cbv.x, v1 = ca.y + cbv.y;
            float v2 = ca.z + cbv.z, v3 = ca.w + cbv.w;
            float m = fmaxf(fmaxf(v0, v1), fmaxf(v2, v3));
            m = fmaxf(m, __shfl_xor_sync(0xffffffffu, m, 1));
            m = fmaxf(m, __shfl_xor_sync(0xffffffffu, m, 2));
            m = fmaxf(m, __shfl_xor_sync(0xffffffffu, m, 4));
            float e0 = __expf(v0 - m), e1 = __expf(v1 - m);
            float e2 = __expf(v2 - m), e3 = __expf(v3 - m);
            float sm = e0 + e1 + e2 + e3;
            sm += __shfl_xor_sync(0xffffffffu, sm, 1);
            sm += __shfl_xor_sync(0xffffffffu, sm, 2);
            sm += __shfl_xor_sync(0xffffffffu, sm, 4);
            float inv = 1.f / sm;
            *(float4*)&sc[s_u * 36 + tn] = make_float4(e0 * inv, e1 * inv, e2 * inv, e3 * inv);
        }
        __syncthreads();
        if (c < 7) {
            int k0 = (c + 1) * 32;
            #pragma unroll
            for (int j = 0; j < 8; ++j)
                uv[j] = *(const float4*)(Ub + (size_t)(sh + k0 + s_u) * DIN + i0 + li + 32 * j);
            ca  = *(const float4*)(l0 + (size_t)(k0 + s_u) * NCAP + tn);
            cbv = *(const float4*)(l1 + (size_t)(k0 + s_u) * NCAP + tn);
        }
        #pragma unroll
        for (int kk = 0; kk < 32; ++kk) {
            float4 c4 = *(const float4*)&sc[kk * 36 + tn];
            float4 u0 = *(const float4*)&su[kk * 260 + ti];
            float4 u1 = *(const float4*)&su[kk * 260 + ti + 4];
            float cvv[4] = {c4.x, c4.y, c4.z, c4.w};
            float uvv[8] = {u0.x, u0.y, u0.z, u0.w, u1.x, u1.y, u1.z, u1.w};
            #pragma unroll
            for (int y = 0; y < 4; ++y)
                #pragma unroll
                for (int x = 0; x < 8; ++x)
                    acc[y][x] += cvv[y] * uvv[x];
        }
    }
    float* vb = g_vp + ((size_t)(blockIdx.y * B_ + b) * NCAP) * DIN + i0;
    #pragma unroll
    for (int y = 0; y < 4; ++y) {
        *(float4*)(vb + (size_t)(tn + y) * DIN + ti) =
            make_float4(acc[y][0], acc[y][1], acc[y][2], acc[y][3]);
        *(float4*)(vb + (size_t)(tn + y) * DIN + ti + 4) =
            make_float4(acc[y][4], acc[y][5], acc[y][6], acc[y][7]);
    }
}

// ---------------- launch ----------------
extern "C" void kernel_launch(void* const* d_in, const int* in_sizes, int n_in,
                              void* d_out, int out_size) {
    const float* U = (const float*)d_in[0];   // (64, 512, 512)
    const float* W = (const float*)d_in[1];   // (512, 2048)
    float* out = (float*)d_out;               // (64, 32, 64)

    prep_k<<<512, 256>>>(U, W);
    outw_k<<<dim3(32, 8), 512>>>(out, 1, 1);             // iteration 0 + w0
    for (int it = 0; it < 2; ++it) {
        blog_k<<<dim3(2, 2, 64), 256>>>(U);
        v_k<<<dim3(2, 2, 64), 256>>>(U);
        outw_k<<<dim3(32, 8), 512>>>(out, 0, it == 0);   // out + (w for iter 1 only)
    }
}

// round 7
// speedup vs baseline: 1.0096x; 1.0096x over previous
#include <cuda_runtime.h>

#define B_    64
#define S_    512
#define DIN   512
#define NCAP  32
#define DCAP  64
#define EPSQ  1e-7f

// ---------------- f32x2 packed-FMA helpers (sm_100a; ptxas never emits these) ----------
__device__ __forceinline__ unsigned long long bcast2(float a) {
    unsigned long long r;
    asm("mov.b64 %0, {%1, %1};" : "=l"(r) : "f"(a));
    return r;
}
__device__ __forceinline__ void ffma2(unsigned long long& d,
                                      unsigned long long a, unsigned long long b) {
    asm("fma.rn.f32x2 %0, %1, %2, %0;" : "+l"(d) : "l"(a), "l"(b));
}

// ---------------- scratch (device globals; no allocations) ----------------
__device__ float g_Wt[NCAP * DCAP * DIN];      // W transposed: [n][d][i]
__device__ float g_tp[4 * B_ * DIN];           // partial column sums of U
__device__ float g_w[B_ * DIN * NCAP];         // w[b][i][n]
__device__ float g_l[2 * B_ * S_ * NCAP];      // raw logit partials [ihalf][b][s][n]
__device__ float g_vp[2 * B_ * NCAP * DIN];    // v partials [shalf][b][n][i]

// ---------------- prep: blocks 0..255 transpose W, 256..511 colsum U ----------------
__global__ __launch_bounds__(256) void prep_k(const float* __restrict__ U,
                                              const float* __restrict__ W) {
    int t = threadIdx.x;
    if (blockIdx.x < 256) {
        int n  = blockIdx.x >> 3;
        int i0 = (blockIdx.x & 7) * 64;
        __shared__ float sm[64 * 65];
        #pragma unroll
        for (int r = 0; r < 16; ++r) {
            int idx = r * 256 + t;
            int d = idx & 63, ii = idx >> 6;
            sm[d * 65 + ii] = W[(size_t)(i0 + ii) * 2048 + n * 64 + d];
        }
        __syncthreads();
        #pragma unroll
        for (int r = 0; r < 16; ++r) {
            int idx = r * 256 + t;
            int ii = idx & 63, d = idx >> 6;
            g_Wt[((size_t)n * 64 + d) * 512 + i0 + ii] = sm[d * 65 + ii];
        }
    } else {
        int idx = blockIdx.x - 256;
        int b = idx & 63, sc = idx >> 6;
        const float2* p = (const float2*)(U + ((size_t)b * S_ + sc * 128) * DIN) + t;
        float2 a = make_float2(0.f, 0.f);
        #pragma unroll 8
        for (int s = 0; s < 128; ++s) {
            float2 f = p[(size_t)s * 256];
            a.x += f.x; a.y += f.y;
        }
        *(float2*)(g_tp + ((size_t)sc * B_ + b) * DIN + t * 2) = a;
    }
}

// ---------------- fused out + w ----------------
__global__ __launch_bounds__(512) void outw_k(float* __restrict__ out, int bcast, int dow) {
    int n  = blockIdx.x;
    int b0 = blockIdx.y * 8;
    __shared__ __align__(16) float sv[8][DIN];
    __shared__ float so[8][DCAP];
    int t = threadIdx.x, w = t >> 5, lane = t & 31;
    const float* Wn = g_Wt + (size_t)n * DCAP * DIN;

    #pragma unroll
    for (int r = 0; r < 8; ++r) {
        int idx = r * 512 + t;
        int bb = idx >> 9, pos = idx & 511;
        int b = b0 + bb;
        float val;
        if (bcast)
            val = g_tp[(size_t)b * DIN + pos]
                + g_tp[((size_t)B_ + b) * DIN + pos]
                + g_tp[((size_t)2 * B_ + b) * DIN + pos]
                + g_tp[((size_t)3 * B_ + b) * DIN + pos];
        else
            val = g_vp[((size_t)b * NCAP + n) * DIN + pos]
                + g_vp[((size_t)(B_ + b) * NCAP + n) * DIN + pos];
        sv[bb][pos] = val;
    }
    __syncthreads();

    #pragma unroll
    for (int r = 0; r < 4; ++r) {
        int d = r * 16 + w;
        const float4* wp = (const float4*)(Wn + (size_t)d * DIN);
        float acc[8] = {};
        #pragma unroll
        for (int q = 0; q < 4; ++q) {
            float4 wv = wp[lane + q * 32];
            #pragma unroll
            for (int bb = 0; bb < 8; ++bb) {
                float4 vv = ((const float4*)sv[bb])[lane + q * 32];
                acc[bb] += wv.x * vv.x + wv.y * vv.y + wv.z * vv.z + wv.w * vv.w;
            }
        }
        #pragma unroll
        for (int bb = 0; bb < 8; ++bb) {
            #pragma unroll
            for (int off = 16; off; off >>= 1)
                acc[bb] += __shfl_xor_sync(0xffffffffu, acc[bb], off);
        }
        if (lane == 0) {
            #pragma unroll
            for (int bb = 0; bb < 8; ++bb) so[bb][d] = acc[bb];
        }
    }
    __syncthreads();

    if (w < 8) {
        int b = b0 + w;
        float o1 = so[w][lane], o2 = so[w][lane + 32];
        if (bcast) { o1 *= (1.f / 32.f); o2 *= (1.f / 32.f); }
        float sq = o1 * o1 + o2 * o2;
        #pragma unroll
        for (int off = 16; off; off >>= 1) sq += __shfl_xor_sync(0xffffffffu, sq, off);
        float rn = rsqrtf(sq + EPSQ);
        o1 *= rn; o2 *= rn;
        out[((size_t)b * NCAP + n) * DCAP + lane]      = o1;
        out[((size_t)b * NCAP + n) * DCAP + lane + 32] = o2;
        so[w][lane]      = o1;
        so[w][lane + 32] = o2;
    }
    __syncthreads();

    if (dow) {
        int i = t;
        float acc[8] = {};
        #pragma unroll 8
        for (int d = 0; d < DCAP; ++d) {
            float wt = Wn[(size_t)d * DIN + i];
            #pragma unroll
            for (int bb = 0; bb < 8; ++bb) acc[bb] += so[bb][d] * wt;
        }
        #pragma unroll
        for (int bb = 0; bb < 8; ++bb)
            g_w[((size_t)(b0 + bb) * DIN + i) * NCAP + n] = acc[bb];
    }
}

// ---------------- logit partials: tile 256s x 32n over 256 i's (f32x2 core) ----------
// grid (2 s-tiles, 2 i-halves, 64 b) = 256 blocks, thread 8s x 4n (2 n-pairs).
__global__ __launch_bounds__(256, 2) void blog_k(const float* __restrict__ U) {
    int s0 = blockIdx.x * 256;
    int ih = blockIdx.y * 256;
    int b  = blockIdx.z;
    __shared__ __align__(16) float su[256 * 36];  // [s][k]
    __shared__ __align__(16) float sw[32 * 36];   // [k][n]
    int t  = threadIdx.x;
    int tn = (t & 7) * 4, ts = (t >> 3) * 8;
    int lrow = t >> 3, lk = (t & 7) * 4;
    const float* Ub    = U   + (size_t)b * S_ * DIN + ih;
    const float* wbase = g_w + (size_t)b * DIN * NCAP + (size_t)ih * NCAP;
    float4 ua[8], wv;
    #pragma unroll
    for (int j = 0; j < 8; ++j)
        ua[j] = *(const float4*)(Ub + (size_t)(s0 + lrow + 32 * j) * DIN + lk);
    wv = *(const float4*)(wbase + (size_t)lrow * NCAP + tn);
    unsigned long long acc2[8][2] = {};
    #pragma unroll 1
    for (int c = 0; c < 8; ++c) {
        __syncthreads();
        #pragma unroll
        for (int j = 0; j < 8; ++j)
            *(float4*)&su[(lrow + 32 * j) * 36 + lk] = ua[j];
        *(float4*)&sw[lrow * 36 + tn] = wv;
        __syncthreads();
        if (c < 7) {
            int k0 = (c + 1) * 32;
            #pragma unroll
            for (int j = 0; j < 8; ++j)
                ua[j] = *(const float4*)(Ub + (size_t)(s0 + lrow + 32 * j) * DIN + k0 + lk);
            wv = *(const float4*)(wbase + (size_t)(k0 + lrow) * NCAP + tn);
        }
        #pragma unroll
        for (int kk = 0; kk < 32; kk += 4) {
            ulonglong2 wq2[4];
            float4 sv4[8];
            #pragma unroll
            for (int q = 0; q < 4; ++q)
                wq2[q] = *(const ulonglong2*)&sw[(kk + q) * 36 + tn];
            #pragma unroll
            for (int x = 0; x < 8; ++x)
                sv4[x] = *(const float4*)&su[(ts + x) * 36 + kk];
            #pragma unroll
            for (int q = 0; q < 4; ++q) {
                #pragma unroll
                for (int x = 0; x < 8; ++x) {
                    float a = (q == 0) ? sv4[x].x : (q == 1) ? sv4[x].y
                            : (q == 2) ? sv4[x].z : sv4[x].w;
                    unsigned long long ap = bcast2(a);
                    ffma2(acc2[x][0], ap, wq2[q].x);
                    ffma2(acc2[x][1], ap, wq2[q].y);
                }
            }
        }
    }
    float* lb = g_l + (((size_t)blockIdx.y * B_ + b) * S_ + s0) * NCAP;
    #pragma unroll
    for (int x = 0; x < 8; ++x) {
        ulonglong2 o; o.x = acc2[x][0]; o.y = acc2[x][1];
        *(ulonglong2*)(lb + (size_t)(ts + x) * NCAP + tn) = o;
    }
}

// ---------------- v partials: tile 32n x 256i over 256 s's (f32x2 core) ----------
// grid (2 i-tiles, 2 s-halves, 64 b) = 256 blocks, thread 4n x 8i (4 i-pairs).
__global__ __launch_bounds__(256, 2) void v_k(const float* __restrict__ U) {
    int i0 = blockIdx.x * 256;
    int sh = blockIdx.y * 256;
    int b  = blockIdx.z;
    __shared__ __align__(16) float su[32 * 260];  // [s][i]
    __shared__ __align__(16) float sc[32 * 36];   // [s][n]
    int t  = threadIdx.x;
    int tn = (t & 7) * 4, ti = (t >> 3) * 8;
    int s_u = t >> 3, li = (t & 7) * 4;
    const float* Ub = U + (size_t)b * S_ * DIN;
    const float* l0 = g_l + ((size_t)b * S_ + sh) * NCAP;
    const float* l1 = g_l + (((size_t)B_ + b) * S_ + sh) * NCAP;
    float4 uv[8], ca, cbv;
    #pragma unroll
    for (int j = 0; j < 8; ++j)
        uv[j] = *(const float4*)(Ub + (size_t)(sh + s_u) * DIN + i0 + li + 32 * j);
    ca  = *(const float4*)(l0 + (size_t)s_u * NCAP + tn);
    cbv = *(const float4*)(l1 + (size_t)s_u * NCAP + tn);
    unsigned long long acc2[4][4] = {};
    #pragma unroll 1
    for (int c = 0; c < 8; ++c) {
        __syncthreads();
        #pragma unroll
        for (int j = 0; j < 8; ++j)
            *(float4*)&su[s_u * 260 + li + 32 * j] = uv[j];
        {   // combine logit halves + softmax over n (8 lanes share s-row; xor 1,2,4)
            float v0 = ca.x + cbv.x, v1 = ca.y + cbv.y;
            float v2 = ca.z + cbv.z, v3 = ca.w + cbv.w;
            float m = fmaxf(fmaxf(v0, v1), fmaxf(v2, v3));
            m = fmaxf(m, __shfl_xor_sync(0xffffffffu, m, 1));
            m = fmaxf(m, __shfl_xor_sync(0xffffffffu, m, 2));
            m = fmaxf(m, __shfl_xor_sync(0xffffffffu, m, 4));
            float e0 = __expf(v0 - m), e1 = __expf(v1 - m);
            float e2 = __expf(v2 - m), e3 = __expf(v3 - m);
            float sm = e0 + e1 + e2 + e3;
            sm += __shfl_xor_sync(0xffffffffu, sm, 1);
            sm += __shfl_xor_sync(0xffffffffu, sm, 2);
            sm += __shfl_xor_sync(0xffffffffu, sm, 4);
            float inv = 1.f / sm;
            *(float4*)&sc[s_u * 36 + tn] = make_float4(e0 * inv, e1 * inv, e2 * inv, e3 * inv);
        }
        __syncthreads();
        if (c < 7) {
            int k0 = (c + 1) * 32;
            #pragma unroll
            for (int j = 0; j < 8; ++j)
                uv[j] = *(const float4*)(Ub + (size_t)(sh + k0 + s_u) * DIN + i0 + li + 32 * j);
            ca  = *(const float4*)(l0 + (size_t)(k0 + s_u) * NCAP + tn);
            cbv = *(const float4*)(l1 + (size_t)(k0 + s_u) * NCAP + tn);
        }
        #pragma unroll
        for (int kk = 0; kk < 32; ++kk) {
            float4 c4 = *(const float4*)&sc[kk * 36 + tn];
            ulonglong2 u01 = *(const ulonglong2*)&su[kk * 260 + ti];
            ulonglong2 u23 = *(const ulonglong2*)&su[kk * 260 + ti + 4];
            unsigned long long up[4] = {u01.x, u01.y, u23.x, u23.y};
            unsigned long long cp[4] = {bcast2(c4.x), bcast2(c4.y), bcast2(c4.z), bcast2(c4.w)};
            #pragma unroll
            for (int y = 0; y < 4; ++y) {
                #pragma unroll
                for (int p = 0; p < 4; ++p)
                    ffma2(acc2[y][p], cp[y], up[p]);
            }
        }
    }
    float* vb = g_vp + ((size_t)(blockIdx.y * B_ + b) * NCAP) * DIN + i0;
    #pragma unroll
    for (int y = 0; y < 4; ++y) {
        ulonglong2 o0; o0.x = acc2[y][0]; o0.y = acc2[y][1];
        ulonglong2 o1; o1.x = acc2[y][2]; o1.y = acc2[y][3];
        *(ulonglong2*)(vb + (size_t)(tn + y) * DIN + ti)     = o0;
        *(ulonglong2*)(vb + (size_t)(tn + y) * DIN + ti + 4) = o1;
    }
}

// ---------------- launch ----------------
extern "C" void kernel_launch(void* const* d_in, const int* in_sizes, int n_in,
                              void* d_out, int out_size) {
    const float* U = (const float*)d_in[0];   // (64, 512, 512)
    const float* W = (const float*)d_in[1];   // (512, 2048)
    float* out = (float*)d_out;               // (64, 32, 64)

    prep_k<<<512, 256>>>(U, W);
    outw_k<<<dim3(32, 8), 512>>>(out, 1, 1);             // iteration 0 + w0
    for (int it = 0; it < 2; ++it) {
        blog_k<<<dim3(2, 2, 64), 256>>>(U);
        v_k<<<dim3(2, 2, 64), 256>>>(U);
        outw_k<<<dim3(32, 8), 512>>>(out, 0, it == 0);   // out + (w for iter 1 only)
    }
}

// round 8
// speedup vs baseline: 1.2326x; 1.2209x over previous
#include <cuda_runtime.h>
#include <cstdint>

#define B_    64
#define S_    512
#define DIN   512
#define NCAP  32
#define DCAP  64
#define EPSQ  1e-7f

// ---------------- scratch (device globals; no allocations) ----------------
__device__ float g_Wt[NCAP * DCAP * DIN];      // W transposed: [n][d][i]
__device__ float g_tp[4 * B_ * DIN];           // partial column sums of U
__device__ float g_w[B_ * DIN * NCAP];         // w[b][i][n]
__device__ float g_c[B_ * S_ * NCAP];          // c[b][s][n] (post-softmax)
__device__ float g_v[B_ * NCAP * DIN];         // v[b][n][i]

// ---------------- tf32 helpers ----------------
__device__ __forceinline__ uint32_t tf32r(float x) {
    uint32_t r;
    asm("cvt.rna.tf32.f32 %0, %1;" : "=r"(r) : "f"(x));
    return r;
}
__device__ __forceinline__ void mma_tf32(float& c0, float& c1, float& c2, float& c3,
                                         uint32_t a0, uint32_t a1, uint32_t a2, uint32_t a3,
                                         uint32_t b0, uint32_t b1) {
    asm("mma.sync.aligned.m16n8k8.row.col.f32.tf32.tf32.f32 "
        "{%0,%1,%2,%3}, {%4,%5,%6,%7}, {%8,%9}, {%0,%1,%2,%3};"
        : "+f"(c0), "+f"(c1), "+f"(c2), "+f"(c3)
        : "r"(a0), "r"(a1), "r"(a2), "r"(a3), "r"(b0), "r"(b1));
}

// ---------------- prep: blocks 0..255 transpose W, 256..511 colsum U ----------------
__global__ __launch_bounds__(256) void prep_k(const float* __restrict__ U,
                                              const float* __restrict__ W) {
    int t = threadIdx.x;
    if (blockIdx.x < 256) {
        int n  = blockIdx.x >> 3;
        int i0 = (blockIdx.x & 7) * 64;
        __shared__ float sm[64 * 65];
        #pragma unroll
        for (int r = 0; r < 16; ++r) {
            int idx = r * 256 + t;
            int d = idx & 63, ii = idx >> 6;
            sm[d * 65 + ii] = W[(size_t)(i0 + ii) * 2048 + n * 64 + d];
        }
        __syncthreads();
        #pragma unroll
        for (int r = 0; r < 16; ++r) {
            int idx = r * 256 + t;
            int ii = idx & 63, d = idx >> 6;
            g_Wt[((size_t)n * 64 + d) * 512 + i0 + ii] = sm[d * 65 + ii];
        }
    } else {
        int idx = blockIdx.x - 256;
        int b = idx & 63, sc = idx >> 6;
        const float2* p = (const float2*)(U + ((size_t)b * S_ + sc * 128) * DIN) + t;
        float2 a = make_float2(0.f, 0.f);
        #pragma unroll 8
        for (int s = 0; s < 128; ++s) {
            float2 f = p[(size_t)s * 256];
            a.x += f.x; a.y += f.y;
        }
        *(float2*)(g_tp + ((size_t)sc * B_ + b) * DIN + t * 2) = a;
    }
}

// ---------------- fused out + w (fp32, unchanged structure) ----------------
__global__ __launch_bounds__(512) void outw_k(float* __restrict__ out, int bcast, int dow) {
    int n  = blockIdx.x;
    int b0 = blockIdx.y * 8;
    __shared__ __align__(16) float sv[8][DIN];
    __shared__ float so[8][DCAP];
    int t = threadIdx.x, w = t >> 5, lane = t & 31;
    const float* Wn = g_Wt + (size_t)n * DCAP * DIN;

    #pragma unroll
    for (int r = 0; r < 8; ++r) {
        int idx = r * 512 + t;
        int bb = idx >> 9, pos = idx & 511;
        int b = b0 + bb;
        float val;
        if (bcast)
            val = g_tp[(size_t)b * DIN + pos]
                + g_tp[((size_t)B_ + b) * DIN + pos]
                + g_tp[((size_t)2 * B_ + b) * DIN + pos]
                + g_tp[((size_t)3 * B_ + b) * DIN + pos];
        else
            val = g_v[((size_t)b * NCAP + n) * DIN + pos];
        sv[bb][pos] = val;
    }
    __syncthreads();

    #pragma unroll
    for (int r = 0; r < 4; ++r) {
        int d = r * 16 + w;
        const float4* wp = (const float4*)(Wn + (size_t)d * DIN);
        float acc[8] = {};
        #pragma unroll
        for (int q = 0; q < 4; ++q) {
            float4 wv = wp[lane + q * 32];
            #pragma unroll
            for (int bb = 0; bb < 8; ++bb) {
                float4 vv = ((const float4*)sv[bb])[lane + q * 32];
                acc[bb] += wv.x * vv.x + wv.y * vv.y + wv.z * vv.z + wv.w * vv.w;
            }
        }
        #pragma unroll
        for (int bb = 0; bb < 8; ++bb) {
            #pragma unroll
            for (int off = 16; off; off >>= 1)
                acc[bb] += __shfl_xor_sync(0xffffffffu, acc[bb], off);
        }
        if (lane == 0) {
            #pragma unroll
            for (int bb = 0; bb < 8; ++bb) so[bb][d] = acc[bb];
        }
    }
    __syncthreads();

    if (w < 8) {
        int b = b0 + w;
        float o1 = so[w][lane], o2 = so[w][lane + 32];
        if (bcast) { o1 *= (1.f / 32.f); o2 *= (1.f / 32.f); }
        float sq = o1 * o1 + o2 * o2;
        #pragma unroll
        for (int off = 16; off; off >>= 1) sq += __shfl_xor_sync(0xffffffffu, sq, off);
        float rn = rsqrtf(sq + EPSQ);
        o1 *= rn; o2 *= rn;
        out[((size_t)b * NCAP + n) * DCAP + lane]      = o1;
        out[((size_t)b * NCAP + n) * DCAP + lane + 32] = o2;
        so[w][lane]      = o1;
        so[w][lane + 32] = o2;
    }
    __syncthreads();

    if (dow) {
        int i = t;
        float acc[8] = {};
        #pragma unroll 8
        for (int d = 0; d < DCAP; ++d) {
            float wt = Wn[(size_t)d * DIN + i];
            #pragma unroll
            for (int bb = 0; bb < 8; ++bb) acc[bb] += so[bb][d] * wt;
        }
        #pragma unroll
        for (int bb = 0; bb < 8; ++bb)
            g_w[((size_t)(b0 + bb) * DIN + i) * NCAP + n] = acc[bb];
    }
}

// ---------------- tf32 MMA: logits[s,n] = U[s,:]·w[:,n], softmax fused ----------------
// grid (4 s-tiles, 64 b), block 128 (4 warps). Tile 128s x 32n, K=i=512 in chunks of 32.
// Warp owns 32 s (2 m16) x 32 n (4 n8).
__global__ __launch_bounds__(128, 4) void blogmma_k(const float* __restrict__ U) {
    int s0 = blockIdx.x * 128;
    int b  = blockIdx.y;
    __shared__ uint32_t su[128 * 36];   // tf32 bits [s][k-chunk]
    __shared__ uint32_t sw[32 * 36];    // tf32 bits [k][n]
    int t = threadIdx.x, w = t >> 5, lane = t & 31;
    int g = lane >> 2, tg = lane & 3;
    int wrow = w * 32;
    int lrow = t >> 2, lc = (t & 3) * 8;   // loader coords
    const float* Ub = U   + ((size_t)b * S_ + s0) * DIN;
    const float* wb = g_w + (size_t)b * DIN * NCAP;
    float c[2][4][4] = {};
    float4 pu[8], pw[2];
    #pragma unroll
    for (int r = 0; r < 4; ++r) {
        pu[2 * r]     = *(const float4*)(Ub + (size_t)(lrow + 32 * r) * DIN + lc);
        pu[2 * r + 1] = *(const float4*)(Ub + (size_t)(lrow + 32 * r) * DIN + lc + 4);
    }
    pw[0] = *(const float4*)(wb + (size_t)lrow * NCAP + lc);
    pw[1] = *(const float4*)(wb + (size_t)lrow * NCAP + lc + 4);

    #pragma unroll 1
    for (int ch = 0; ch < 16; ++ch) {
        __syncthreads();
        #pragma unroll
        for (int r = 0; r < 4; ++r) {
            uint32_t* d0 = &su[(lrow + 32 * r) * 36 + lc];
            float4 a = pu[2 * r], bq = pu[2 * r + 1];
            d0[0] = tf32r(a.x);  d0[1] = tf32r(a.y);  d0[2] = tf32r(a.z);  d0[3] = tf32r(a.w);
            d0[4] = tf32r(bq.x); d0[5] = tf32r(bq.y); d0[6] = tf32r(bq.z); d0[7] = tf32r(bq.w);
        }
        {
            uint32_t* d0 = &sw[lrow * 36 + lc];
            float4 a = pw[0], bq = pw[1];
            d0[0] = tf32r(a.x);  d0[1] = tf32r(a.y);  d0[2] = tf32r(a.z);  d0[3] = tf32r(a.w);
            d0[4] = tf32r(bq.x); d0[5] = tf32r(bq.y); d0[6] = tf32r(bq.z); d0[7] = tf32r(bq.w);
        }
        __syncthreads();
        if (ch < 15) {
            int i0 = (ch + 1) * 32;
            #pragma unroll
            for (int r = 0; r < 4; ++r) {
                pu[2 * r]     = *(const float4*)(Ub + (size_t)(lrow + 32 * r) * DIN + i0 + lc);
                pu[2 * r + 1] = *(const float4*)(Ub + (size_t)(lrow + 32 * r) * DIN + i0 + lc + 4);
            }
            pw[0] = *(const float4*)(wb + (size_t)(i0 + lrow) * NCAP + lc);
            pw[1] = *(const float4*)(wb + (size_t)(i0 + lrow) * NCAP + lc + 4);
        }
        #pragma unroll
        for (int ks = 0; ks < 4; ++ks) {
            int k0 = ks * 8;
            uint32_t bf[4][2];
            #pragma unroll
            for (int nt = 0; nt < 4; ++nt) {
                bf[nt][0] = sw[(k0 + tg) * 36 + nt * 8 + g];
                bf[nt][1] = sw[(k0 + tg + 4) * 36 + nt * 8 + g];
            }
            #pragma unroll
            for (int mt = 0; mt < 2; ++mt) {
                int r0 = wrow + mt * 16;
                uint32_t a0 = su[(r0 + g)     * 36 + k0 + tg];
                uint32_t a1 = su[(r0 + g + 8) * 36 + k0 + tg];
                uint32_t a2 = su[(r0 + g)     * 36 + k0 + tg + 4];
                uint32_t a3 = su[(r0 + g + 8) * 36 + k0 + tg + 4];
                #pragma unroll
                for (int nt = 0; nt < 4; ++nt)
                    mma_tf32(c[mt][nt][0], c[mt][nt][1], c[mt][nt][2], c[mt][nt][3],
                             a0, a1, a2, a3, bf[nt][0], bf[nt][1]);
            }
        }
    }
    // softmax over n per s-row (row's 32 n live on the 4 lanes sharing g: xor 1,2)
    float* cbase = g_c + ((size_t)b * S_ + s0) * NCAP;
    #pragma unroll
    for (int mt = 0; mt < 2; ++mt) {
        #pragma unroll
        for (int half = 0; half < 2; ++half) {
            int row = wrow + mt * 16 + g + half * 8;
            float v0 = c[mt][0][half * 2], v1 = c[mt][0][half * 2 + 1];
            float v2 = c[mt][1][half * 2], v3 = c[mt][1][half * 2 + 1];
            float v4 = c[mt][2][half * 2], v5 = c[mt][2][half * 2 + 1];
            float v6 = c[mt][3][half * 2], v7 = c[mt][3][half * 2 + 1];
            float m = fmaxf(fmaxf(fmaxf(v0, v1), fmaxf(v2, v3)),
                            fmaxf(fmaxf(v4, v5), fmaxf(v6, v7)));
            m = fmaxf(m, __shfl_xor_sync(0xffffffffu, m, 1));
            m = fmaxf(m, __shfl_xor_sync(0xffffffffu, m, 2));
            float e0 = __expf(v0 - m), e1 = __expf(v1 - m), e2 = __expf(v2 - m), e3 = __expf(v3 - m);
            float e4 = __expf(v4 - m), e5 = __expf(v5 - m), e6 = __expf(v6 - m), e7 = __expf(v7 - m);
            float sm = e0 + e1 + e2 + e3 + e4 + e5 + e6 + e7;
            sm += __shfl_xor_sync(0xffffffffu, sm, 1);
            sm += __shfl_xor_sync(0xffffffffu, sm, 2);
            float inv = 1.f / sm;
            float* cr = cbase + (size_t)row * NCAP + 2 * tg;
            *(float2*)(cr)      = make_float2(e0 * inv, e1 * inv);
            *(float2*)(cr + 8)  = make_float2(e2 * inv, e3 * inv);
            *(float2*)(cr + 16) = make_float2(e4 * inv, e5 * inv);
            *(float2*)(cr + 24) = make_float2(e6 * inv, e7 * inv);
        }
    }
}

// ---------------- tf32 MMA: v[n,i] = sum_s c[s,n] U[s,i] (as v^T[i,n], then transpose) --
// grid (4 i-tiles, 64 b), block 128 (4 warps). Tile 128i x 32n, K=s=512 in chunks of 32.
// A = U^T (m=i, k=s), B = c (k=s, n). Warp owns 32 i (2 m16) x 32 n (4 n8).
__global__ __launch_bounds__(128, 4) void vmma_k(const float* __restrict__ U) {
    int i0 = blockIdx.x * 128;
    int b  = blockIdx.y;
    __shared__ uint32_t su[32 * 132];   // tf32 bits [s][i]  (reused as vsm[128][33])
    __shared__ uint32_t scm[32 * 36];   // tf32 bits [s][n]
    int t = threadIdx.x, w = t >> 5, lane = t & 31;
    int g = lane >> 2, tg = lane & 3;
    int wi = w * 32;
    int lrow = t >> 2, l4 = (t & 3) * 4, lc = (t & 3) * 8;
    const float* Ub = U + (size_t)b * S_ * DIN;
    const float* cb = g_c + (size_t)b * S_ * NCAP;
    float c[2][4][4] = {};
    float4 pu[8], pc[2];
    #pragma unroll
    for (int q = 0; q < 8; ++q)
        pu[q] = *(const float4*)(Ub + (size_t)lrow * DIN + i0 + l4 + 16 * q);
    pc[0] = *(const float4*)(cb + (size_t)lrow * NCAP + lc);
    pc[1] = *(const float4*)(cb + (size_t)lrow * NCAP + lc + 4);

    #pragma unroll 1
    for (int ch = 0; ch < 16; ++ch) {
        __syncthreads();
        #pragma unroll
        for (int q = 0; q < 8; ++q) {
            uint32_t* d0 = &su[lrow * 132 + l4 + 16 * q];
            float4 a = pu[q];
            d0[0] = tf32r(a.x); d0[1] = tf32r(a.y); d0[2] = tf32r(a.z); d0[3] = tf32r(a.w);
        }
        {
            uint32_t* d0 = &scm[lrow * 36 + lc];
            float4 a = pc[0], bq = pc[1];
            d0[0] = tf32r(a.x);  d0[1] = tf32r(a.y);  d0[2] = tf32r(a.z);  d0[3] = tf32r(a.w);
            d0[4] = tf32r(bq.x); d0[5] = tf32r(bq.y); d0[6] = tf32r(bq.z); d0[7] = tf32r(bq.w);
        }
        __syncthreads();
        if (ch < 15) {
            int s1 = (ch + 1) * 32;
            #pragma unroll
            for (int q = 0; q < 8; ++q)
                pu[q] = *(const float4*)(Ub + (size_t)(s1 + lrow) * DIN + i0 + l4 + 16 * q);
            pc[0] = *(const float4*)(cb + (size_t)(s1 + lrow) * NCAP + lc);
            pc[1] = *(const float4*)(cb + (size_t)(s1 + lrow) * NCAP + lc + 4);
        }
        #pragma unroll
        for (int ks = 0; ks < 4; ++ks) {
            int k0 = ks * 8;
            uint32_t bf[4][2];
            #pragma unroll
            for (int nt = 0; nt < 4; ++nt) {
                bf[nt][0] = scm[(k0 + tg) * 36 + nt * 8 + g];
                bf[nt][1] = scm[(k0 + tg + 4) * 36 + nt * 8 + g];
            }
            #pragma unroll
            for (int mt = 0; mt < 2; ++mt) {
                int ib = wi + mt * 16;
                uint32_t a0 = su[(k0 + tg)     * 132 + ib + g];
                uint32_t a1 = su[(k0 + tg)     * 132 + ib + g + 8];
                uint32_t a2 = su[(k0 + tg + 4) * 132 + ib + g];
                uint32_t a3 = su[(k0 + tg + 4) * 132 + ib + g + 8];
                #pragma unroll
                for (int nt = 0; nt < 4; ++nt)
                    mma_tf32(c[mt][nt][0], c[mt][nt][1], c[mt][nt][2], c[mt][nt][3],
                             a0, a1, a2, a3, bf[nt][0], bf[nt][1]);
            }
        }
    }
    // transpose v^T[i][n] -> v[n][i] via smem, then coalesced store
    __syncthreads();
    float* vsm = (float*)su;   // 128 x 33 = 4224 floats <= 32*132
    #pragma unroll
    for (int mt = 0; mt < 2; ++mt) {
        int ib = wi + mt * 16;
        #pragma unroll
        for (int nt = 0; nt < 4; ++nt) {
            int nc = nt * 8 + 2 * tg;
            vsm[(ib + g)     * 33 + nc]     = c[mt][nt][0];
            vsm[(ib + g)     * 33 + nc + 1] = c[mt][nt][1];
            vsm[(ib + g + 8) * 33 + nc]     = c[mt][nt][2];
            vsm[(ib + g + 8) * 33 + nc + 1] = c[mt][nt][3];
        }
    }
    __syncthreads();
    {
        int n = t >> 2, igrp = t & 3;
        float* vb = g_v + ((size_t)b * NCAP + n) * DIN + i0;
        #pragma unroll
        for (int q = 0; q < 8; ++q) {
            int i4 = igrp * 4 + q * 16;
            float4 o = make_float4(vsm[(i4 + 0) * 33 + n], vsm[(i4 + 1) * 33 + n],
                                   vsm[(i4 + 2) * 33 + n], vsm[(i4 + 3) * 33 + n]);
            *(float4*)(vb + i4) = o;
        }
    }
}

// ---------------- launch ----------------
extern "C" void kernel_launch(void* const* d_in, const int* in_sizes, int n_in,
                              void* d_out, int out_size) {
    const float* U = (const float*)d_in[0];   // (64, 512, 512)
    const float* W = (const float*)d_in[1];   // (512, 2048)
    float* out = (float*)d_out;               // (64, 32, 64)

    prep_k<<<512, 256>>>(U, W);
    outw_k<<<dim3(32, 8), 512>>>(out, 1, 1);             // iteration 0 + w0
    for (int it = 0; it < 2; ++it) {
        blogmma_k<<<dim3(4, 64), 128>>>(U);
        vmma_k<<<dim3(4, 64), 128>>>(U);
        outw_k<<<dim3(32, 8), 512>>>(out, 0, it == 0);   // out + (w for iter 1 only)
    }
}